// round 6
// baseline (speedup 1.0000x reference)
#include <cuda_runtime.h>
#include <cstdint>

#define NTOK 65536
#define KCB  8192
#define DDIM 64
#define DECAYF 0.9f
#define EPSF 1e-5f

// ---- scratch (no allocation allowed) ----
__device__ float g_cnorm[KCB];
__device__ int   g_token[NTOK];
__device__ float g_counts[KCB];
__device__ float g_embed_sum[KCB * DDIM];
__device__ float g_qerr;
__device__ float g_nsum;
// code-major, k-permuted split codebook: g_w3p[c][p(k)], k<64 hi, k>=64 lo
__device__ __align__(16) float g_w3p[(size_t)KCB * 128];

// ================= helpers =================
__device__ __forceinline__ uint32_t smem_u32(const void* p) {
    uint32_t a;
    asm("{ .reg .u64 t; cvta.to.shared.u64 t, %1; cvt.u32.u64 %0, t; }" : "=r"(a) : "l"(p));
    return a;
}
__device__ __forceinline__ uint32_t tf32r(float x) {
    uint32_t u; asm("cvt.rna.tf32.f32 %0, %1;" : "=r"(u) : "f"(x)); return u;
}
__device__ __forceinline__ void cp16(uint32_t dst, const void* src) {
    asm volatile("cp.async.ca.shared.global [%0], [%1], 16;" :: "r"(dst), "l"(src));
}
__device__ __forceinline__ void mma8(float* c, const uint32_t* a, uint32_t b0, uint32_t b1) {
    asm volatile("mma.sync.aligned.m16n8k8.row.col.f32.tf32.tf32.f32 "
        "{%0,%1,%2,%3},{%4,%5,%6,%7},{%8,%9},{%0,%1,%2,%3};"
        : "+f"(c[0]), "+f"(c[1]), "+f"(c[2]), "+f"(c[3])
        : "r"(a[0]), "r"(a[1]), "r"(a[2]), "r"(a[3]), "r"(b0), "r"(b1));
}

// ================= small kernels =================
__global__ void k_zero() {
    int i = blockIdx.x * blockDim.x + threadIdx.x;
    if (i < KCB * DDIM) g_embed_sum[i] = 0.0f;
    if (i < KCB)        g_counts[i]    = 0.0f;
    if (i == 0) { g_qerr = 0.0f; g_nsum = 0.0f; }
}

__global__ void k_cnorm(const float* __restrict__ w) {
    int warp = (blockIdx.x * blockDim.x + threadIdx.x) >> 5;
    int lane = threadIdx.x & 31;
    if (warp >= KCB) return;
    float v0 = w[warp * DDIM + lane];
    float v1 = w[warp * DDIM + 32 + lane];
    float s = v0 * v0 + v1 * v1;
    #pragma unroll
    for (int o = 16; o; o >>= 1) s += __shfl_xor_sync(0xffffffffu, s, o);
    if (lane == 0) g_cnorm[warp] = s;
}

// g_w3p[c][q]: q = p(kk) permuted position; kk<64 -> tf32_hi(w[c][kk]), else lo
__global__ void k_prep(const float* __restrict__ w) {
    int i = blockIdx.x * blockDim.x + threadIdx.x;
    if (i >= KCB * 128) return;
    int c = i >> 7, q = i & 127;
    int blk = q >> 3, off = q & 7;
    int kk = blk * 8 + ((off & 1) << 2) + (off >> 1);   // inverse of p()
    float v = w[(size_t)c * DDIM + (kk & 63)];
    uint32_t hi = tf32r(v);
    uint32_t out = (kk < 64) ? hi : tf32r(v - __uint_as_float(hi));
    ((uint32_t*)g_w3p)[i] = out;
}

// ================= main tensor-core kernel =================
static constexpr int AST   = 136;                    // A row stride (floats)
static constexpr int BST   = 136;                    // B code-row stride (floats)
static constexpr int SM_A  = 0;                      // 128*136*4 = 69632
static constexpr int SM_B  = 69632;
static constexpr int B_BUF = 64 * BST * 4;           // 34816
static constexpr int SM_CN = SM_B + 2 * B_BUF;       // 139264
static constexpr int SMEM_TC = SM_CN + KCB * 4;      // 172032

__global__ __launch_bounds__(256, 1) void k_main_tc(const float* __restrict__ z) {
    extern __shared__ char smem[];
    float* As = (float*)(smem + SM_A);
    float* Bs = (float*)(smem + SM_B);
    float* CN = (float*)(smem + SM_CN);
    const uint32_t sbB = smem_u32(Bs);

    const int tid  = threadIdx.x;
    const int lane = tid & 31, wid = tid >> 5;
    const int g    = lane >> 2, tg = lane & 3, tg2 = 2 * tg;
    const int wr   = wid & 3,  wc = wid >> 2;
    const int tok0 = blockIdx.x * 128;

    // ---- all ||c||^2 into smem ----
    #pragma unroll
    for (int i = 0; i < 8; i++) {
        int q = i * 256 + tid;
        *(float4*)(CN + q * 4) = *(const float4*)(g_cnorm + q * 4);
    }
    // ---- stage A permuted: hi at p(c), lo at p(c)+64 ----
    #pragma unroll
    for (int i = 0; i < 8; i++) {
        int q = i * 256 + tid;                       // 2048 float4
        int row = q >> 4, c4 = q & 15;
        float4 v = *(const float4*)(z + (size_t)(tok0 + row) * DDIM + c4 * 4);
        float* dst = As + row * AST + (c4 >> 1) * 8 + (c4 & 1);
        float vv[4] = {v.x, v.y, v.z, v.w};
        #pragma unroll
        for (int j = 0; j < 4; j++) {
            float hi = __uint_as_float(tf32r(vv[j]));
            dst[2 * j]      = hi;
            dst[2 * j + 64] = __uint_as_float(tf32r(vv[j] - hi));
        }
    }
    // ---- prefetch B tile 0 ----
    #pragma unroll
    for (int i = 0; i < 8; i++) {
        int q = i * 256 + tid;                       // 2048 x 16B
        int n = q >> 5, seg = q & 31;
        cp16(sbB + (uint32_t)(n * BST + seg * 4) * 4,
             g_w3p + (size_t)n * 128 + seg * 4);
    }
    asm volatile("cp.async.commit_group;");
    __syncthreads();

    float bv[4];  int bix[4];
    #pragma unroll
    for (int r = 0; r < 4; r++) { bv[r] = 3.4e38f; bix[r] = 0; }

    const float* arow = As + (wr * 32 + g) * AST;

    for (int t = 0; t < 128; t++) {
        const int buf = t & 1;
        if (t < 127) {
            const uint32_t dstb = sbB + (uint32_t)(buf ^ 1) * B_BUF;
            const float* srcb = g_w3p + (size_t)(t + 1) * 64 * 128;
            #pragma unroll
            for (int i = 0; i < 8; i++) {
                int q = i * 256 + tid;
                int n = q >> 5, seg = q & 31;
                cp16(dstb + (uint32_t)(n * BST + seg * 4) * 4,
                     srcb + (size_t)n * 128 + seg * 4);
            }
            asm volatile("cp.async.commit_group;");
            asm volatile("cp.async.wait_group 1;");
        } else {
            asm volatile("cp.async.wait_group 0;");
        }
        __syncthreads();

        const float* B = Bs + buf * (64 * BST);
        float acc[2][4][4];
        #pragma unroll
        for (int m = 0; m < 2; m++)
            #pragma unroll
            for (int nt = 0; nt < 4; nt++)
                #pragma unroll
                for (int c = 0; c < 4; c++) acc[m][nt][c] = 0.0f;

        #pragma unroll
        for (int s = 0; s < 24; s++) {
            const int ca = (s < 8) ? 8 * s : 8 * (s - 8);   // A cols: hi,hi,lo
            const int kb = (8 * s) & 127;                   // B rows: hi,lo,hi
            float2 a00 = *(const float2*)(arow + ca + tg2);
            float2 a08 = *(const float2*)(arow + 8 * AST + ca + tg2);
            float2 a10 = *(const float2*)(arow + 16 * AST + ca + tg2);
            float2 a18 = *(const float2*)(arow + 24 * AST + ca + tg2);
            uint32_t a0[4] = {__float_as_uint(a00.x), __float_as_uint(a08.x),
                              __float_as_uint(a00.y), __float_as_uint(a08.y)};
            uint32_t a1[4] = {__float_as_uint(a10.x), __float_as_uint(a18.x),
                              __float_as_uint(a10.y), __float_as_uint(a18.y)};
            #pragma unroll
            for (int nt = 0; nt < 4; nt++) {
                float2 bf = *(const float2*)(B + (wc * 32 + nt * 8 + g) * BST + kb + tg2);
                mma8(acc[0][nt], a0, __float_as_uint(bf.x), __float_as_uint(bf.y));
                mma8(acc[1][nt], a1, __float_as_uint(bf.x), __float_as_uint(bf.y));
            }
        }

        // epilogue: dist = cn - 2*dot, running argmin (ascending cols = first-min)
        const int cb = t * 64;
        #pragma unroll
        for (int nt = 0; nt < 4; nt++) {
            const int col = cb + wc * 32 + nt * 8 + tg2;
            const float cn0 = CN[col], cn1 = CN[col + 1];
            #pragma unroll
            for (int m = 0; m < 2; m++) {
                #pragma unroll
                for (int h = 0; h < 2; h++) {
                    const int r = m * 2 + h;
                    float d0 = fmaf(-2.0f, acc[m][nt][h * 2 + 0], cn0);
                    float d1 = fmaf(-2.0f, acc[m][nt][h * 2 + 1], cn1);
                    if (d0 < bv[r]) { bv[r] = d0; bix[r] = col; }
                    if (d1 < bv[r]) { bv[r] = d1; bix[r] = col + 1; }
                }
            }
        }
        __syncthreads();
    }

    // combine across quad lanes (same rows), tie-break smaller index
    #pragma unroll
    for (int r = 0; r < 4; r++) {
        float v = bv[r]; int ix = bix[r];
        #pragma unroll
        for (int o = 1; o < 4; o <<= 1) {
            float v2 = __shfl_xor_sync(0xffffffffu, v, o);
            int   i2 = __shfl_xor_sync(0xffffffffu, ix, o);
            if (v2 < v || (v2 == v && i2 < ix)) { v = v2; ix = i2; }
        }
        bv[r] = v; bix[r] = ix;
    }
    __syncthreads();
    float* sv = Bs;
    int*   si = (int*)(Bs + 256);
    if (tg == 0) {
        #pragma unroll
        for (int m = 0; m < 2; m++)
            #pragma unroll
            for (int h = 0; h < 2; h++) {
                int row = wr * 32 + m * 16 + g + 8 * h;
                sv[wc * 128 + row] = bv[m * 2 + h];
                si[wc * 128 + row] = bix[m * 2 + h];
            }
    }
    __syncthreads();
    if (tid < 128) {
        float v0 = sv[tid], v1 = sv[128 + tid];
        int   i0 = si[tid], i1 = si[128 + tid];
        g_token[tok0 + tid] = (v1 < v0 || (v1 == v0 && i1 < i0)) ? i1 : i0;
    }
}

// ---------------- scatter: counts, embed_sum, quant error ----------------
__global__ void k_scatter(const float* __restrict__ z, const float* __restrict__ w) {
    __shared__ float qs[8];
    int warp = threadIdx.x >> 5;
    int lane = threadIdx.x & 31;
    int n = blockIdx.x * 8 + warp;
    int k = g_token[n];
    float z0 = z[(size_t)n * DDIM + lane];
    float z1 = z[(size_t)n * DDIM + 32 + lane];
    float w0 = w[(size_t)k * DDIM + lane];
    float w1 = w[(size_t)k * DDIM + 32 + lane];
    atomicAdd(&g_embed_sum[k * DDIM + lane], z0);
    atomicAdd(&g_embed_sum[k * DDIM + 32 + lane], z1);
    float d0 = w0 - z0, d1 = w1 - z1;
    float s = d0 * d0 + d1 * d1;
    #pragma unroll
    for (int o = 16; o; o >>= 1) s += __shfl_xor_sync(0xffffffffu, s, o);
    if (lane == 0) { qs[warp] = s; atomicAdd(&g_counts[k], 1.0f); }
    __syncthreads();
    if (threadIdx.x == 0) {
        float t = 0.0f;
        #pragma unroll
        for (int i = 0; i < 8; i++) t += qs[i];
        atomicAdd(&g_qerr, t);
    }
}

__global__ void k_ema1(const float* __restrict__ cs, float* __restrict__ out) {
    __shared__ float red[256];
    int k = blockIdx.x * blockDim.x + threadIdx.x;
    float ncs = cs[k] * DECAYF + (1.0f - DECAYF) * g_counts[k];
    out[1 + KCB * DDIM + k] = ncs;
    red[threadIdx.x] = ncs;
    __syncthreads();
    for (int s = 128; s; s >>= 1) {
        if (threadIdx.x < s) red[threadIdx.x] += red[threadIdx.x + s];
        __syncthreads();
    }
    if (threadIdx.x == 0) atomicAdd(&g_nsum, red[0]);
}

__global__ void k_ema2(const float* __restrict__ ea, float* __restrict__ out) {
    int i = blockIdx.x * blockDim.x + threadIdx.x;
    if (i < KCB * DDIM) {
        float nea = ea[i] * DECAYF + (1.0f - DECAYF) * g_embed_sum[i];
        out[1 + KCB * DDIM + KCB + i] = nea;
        int k = i >> 6;
        float ncs = out[1 + KCB * DDIM + k];
        float n = g_nsum;
        float smoothed = (ncs + EPSF) / (n + (float)KCB * EPSF) * n;
        out[1 + i] = nea / smoothed;
    }
    if (i == 0) out[0] = g_qerr / (float)NTOK;
}

extern "C" void kernel_launch(void* const* d_in, const int* in_sizes, int n_in,
                              void* d_out, int out_size) {
    const float* z  = (const float*)d_in[0];
    const float* w  = (const float*)d_in[1];
    const float* cs = (const float*)d_in[2];
    const float* ea = (const float*)d_in[3];
    float* out = (float*)d_out;

    cudaFuncSetAttribute(k_main_tc, cudaFuncAttributeMaxDynamicSharedMemorySize, SMEM_TC);

    k_zero<<<(KCB * DDIM + 255) / 256, 256>>>();
    k_cnorm<<<KCB / 8, 256>>>(w);
    k_prep<<<(KCB * 128 + 255) / 256, 256>>>(w);
    k_main_tc<<<NTOK / 128, 256, SMEM_TC>>>(z);
    k_scatter<<<NTOK / 8, 256>>>(z, w);
    k_ema1<<<KCB / 256, 256>>>(cs, out);
    k_ema2<<<(KCB * DDIM + 255) / 256, 256>>>(ea, out);
}